// round 17
// baseline (speedup 1.0000x reference)
#include <cuda_runtime.h>
#include <math.h>

// ---------------- problem constants ----------------
#define B_TOTAL   131072
#define SDIM      137
#define AHD       128          // SDIM - ZED - 1
#define ZED       8
#define HID       256
#define NBLK      4
#define STRENGTH  0.1f

// ---------------- tiling ----------------
#define MT        64           // batch-rows per CTA
#define AP        68           // activation pitch (64 + 4 pad), floats
#define KC        32           // K chunk
#define WCH       36           // weight chunk row pitch (32 + 4), floats
#define WBUF      (HID * WCH)  // one weight-chunk buffer
#define NTHREADS  512

#define SMEM_FLOATS (2*HID*AP + 2*WBUF)
#define SMEM_BYTES  (SMEM_FLOATS * 4)

typedef unsigned long long ull;

// XOR swizzle of the 16B group WITHIN a 36-word row (never overlaps rows):
// word offset of group g in row r = r*WCH + ((g ^ ((r>>3)&7)) << 2)
__device__ __forceinline__ int wgrp(int r, int g) {
    return r * WCH + (((g ^ ((r >> 3) & 7))) << 2);
}

// ---------------- f32x2 helpers (FFMA2 — ptxas never emits it from C++) ----
__device__ __forceinline__ ull fma2(ull a, ull b, ull c) {
    ull d;
    asm("fma.rn.f32x2 %0, %1, %2, %3;" : "=l"(d) : "l"(a), "l"(b), "l"(c));
    return d;
}
__device__ __forceinline__ ull dup2(float w) {
    ull d;
    unsigned int u = __float_as_uint(w);
    asm("mov.b64 %0, {%1, %1};" : "=l"(d) : "r"(u));
    return d;
}
__device__ __forceinline__ float2 unpk(ull v) {
    float2 f;
    f.x = __uint_as_float((unsigned int)v);
    f.y = __uint_as_float((unsigned int)(v >> 32));
    return f;
}

// ---------------- precomputed small tensors ----------------
// seq-len-1 attention collapses to a linear map:
// out = x @ (out_w @ Wv)^T + (out_w @ bv + out_b)
__device__ float g_Mta[AHD * AHD];
__device__ float g_cta[AHD];
__device__ float g_Mlm[ZED * ZED];
__device__ float g_clm[ZED];
__device__ float g_b0eff[HID];

__global__ void precompute_kernel(const float* __restrict__ t,
                                  const float* __restrict__ W0,
                                  const float* __restrict__ b0,
                                  const float* __restrict__ lm_in_w,
                                  const float* __restrict__ lm_in_b,
                                  const float* __restrict__ lm_out_w,
                                  const float* __restrict__ lm_out_b,
                                  const float* __restrict__ ta_in_w,
                                  const float* __restrict__ ta_in_b,
                                  const float* __restrict__ ta_out_w,
                                  const float* __restrict__ ta_out_b)
{
    int b   = blockIdx.x;
    int tid = threadIdx.x;
    if (b < AHD) {
        int j = b;
        float acc = 0.f;
        for (int i = 0; i < AHD; i++)
            acc += ta_out_w[j * AHD + i] * ta_in_w[(2 * AHD + i) * AHD + tid];
        g_Mta[j * AHD + tid] = acc;
        if (tid == 0) {
            float c = ta_out_b[j];
            for (int i = 0; i < AHD; i++)
                c += ta_out_w[j * AHD + i] * ta_in_b[2 * AHD + i];
            g_cta[j] = c;
        }
    } else if (b == AHD) {
        if (tid < ZED * ZED) {
            int j = tid >> 3, k = tid & 7;
            float acc = 0.f;
            for (int i = 0; i < ZED; i++)
                acc += lm_out_w[j * ZED + i] * lm_in_w[(2 * ZED + i) * ZED + k];
            g_Mlm[tid] = acc;
        }
        if (tid < ZED) {
            int j = tid;
            float c = lm_out_b[j];
            for (int i = 0; i < ZED; i++)
                c += lm_out_w[j * ZED + i] * lm_in_b[2 * ZED + i];
            g_clm[j] = c;
        }
    } else {
        float ang = t[0] * (6.283185307179586f / 24.0f);
        float sv = sinf(ang), cv = cosf(ang);
        for (int n = tid; n < HID; n += blockDim.x)
            g_b0eff[n] = b0[n] + sv * W0[n * (SDIM + 2) + SDIM]
                               + cv * W0[n * (SDIM + 2) + SDIM + 1];
    }
}

// ---------------- GEMM microkernel ----------------
// 512 threads: tm = tid&7, tn = tid>>3 (0..63).
// C cells per thread: m in {tm*4+i} U {32+tm*4+i} (4 f32x2 pairs), n in {tn*4+j}.
// A stored [k][m] pitch AP; loaded as double2 (16B), halves ARE the f32x2 pairs.
// W chunk stored [n][k] pitch WCH with XOR group swizzle. The thread's 4 rows
// tn*4+j all satisfy n>>3 == tn>>1, so one XOR key per thread: xk = (tn>>1)&7.
__device__ __forceinline__ void mm_chunk(const float* __restrict__ Ab,   // Abuf + kbase*AP + tm*4
                                         const float* __restrict__ Wr,   // Wt(+buf) + tn*4*WCH
                                         int xk,                         // (tn>>1) & 7
                                         ull (&acc)[4][4])
{
#pragma unroll
    for (int k4 = 0; k4 < KC / 4; k4++) {
        const int koff = ((k4 ^ xk) << 2);
        float4 w[4];
#pragma unroll
        for (int j = 0; j < 4; j++)
            w[j] = *(const float4*)(Wr + j * WCH + koff);
#pragma unroll
        for (int kk = 0; kk < 4; kk++) {
            const float* Ar = Ab + (k4 * 4 + kk) * AP;
            double2 a0 = *(const double2*)(Ar);
            double2 a1 = *(const double2*)(Ar + 32);
            ull ap0 = __double_as_longlong(a0.x);
            ull ap1 = __double_as_longlong(a0.y);
            ull ap2 = __double_as_longlong(a1.x);
            ull ap3 = __double_as_longlong(a1.y);
#pragma unroll
            for (int j = 0; j < 4; j++) {
                float wv = (kk == 0) ? w[j].x : (kk == 1) ? w[j].y : (kk == 2) ? w[j].z : w[j].w;
                ull wd = dup2(wv);
                acc[0][j] = fma2(ap0, wd, acc[0][j]);
                acc[1][j] = fma2(ap1, wd, acc[1][j]);
                acc[2][j] = fma2(ap2, wd, acc[2][j]);
                acc[3][j] = fma2(ap3, wd, acc[3][j]);
            }
        }
    }
}

// Prefetch one K-chunk (256 n-rows x 32 k) into registers. pitch4 = row pitch/4.
__device__ __forceinline__ void ld_chunk(const float* __restrict__ src, int pitch4,
                                         int k0, int Nv, float4 (&pf)[4], int tid)
{
    int c4 = tid & 7;
    int r  = tid >> 3;          // 0..63
#pragma unroll
    for (int it = 0; it < 4; it++) {
        int rr = r + it * 64;
        float4 v = make_float4(0.f, 0.f, 0.f, 0.f);
        if (rr < Nv) v = ((const float4*)src)[rr * pitch4 + (k0 >> 2) + c4];
        pf[it] = v;
    }
}

__device__ __forceinline__ void st_chunk(float* __restrict__ buf, const float4 (&pf)[4], int tid)
{
    int c4 = tid & 7;
    int r  = tid >> 3;
#pragma unroll
    for (int it = 0; it < 4; it++)
        *(float4*)(buf + wgrp(r + it * 64, c4)) = pf[it];
}

// Full K-loop GEMM with double-buffered weight chunks.
__device__ __forceinline__ void gemm_chunks(const float* __restrict__ W, int pitch4, int Nv,
                                            int nchunks,
                                            const float* __restrict__ Abuf,
                                            float* __restrict__ Wt,
                                            int tid, int tm, int wtb, int xk,
                                            ull (&acc)[4][4])
{
    float4 pf[4];
    ld_chunk(W, pitch4, 0, Nv, pf, tid);
    __syncthreads();                 // previous users of Wt / activation writers done
    st_chunk(Wt, pf, tid);
    __syncthreads();
    for (int c = 0; c < nchunks; c++) {
        if (c + 1 < nchunks) ld_chunk(W, pitch4, (c + 1) * KC, Nv, pf, tid);
        mm_chunk(Abuf + c * KC * AP + tm * 4, Wt + (c & 1) * WBUF + wtb, xk, acc);
        if (c + 1 < nchunks) st_chunk(Wt + ((c + 1) & 1) * WBUF, pf, tid);
        __syncthreads();
    }
}

#define ZACC(A) do { _Pragma("unroll") for (int _p = 0; _p < 4; _p++) _Pragma("unroll") for (int _j = 0; _j < 4; _j++) (A)[_p][_j] = 0ull; } while (0)

// ---------------- fused main kernel ----------------
__global__ __launch_bounds__(NTHREADS, 1)
void fused_odefunc_kernel(const float* __restrict__ state,
                          const float* __restrict__ W0,
                          const float* __restrict__ blkW1,
                          const float* __restrict__ blkb1,
                          const float* __restrict__ blkW2,
                          const float* __restrict__ blkb2,
                          const float* __restrict__ Wout,
                          const float* __restrict__ bout,
                          float* __restrict__ out)
{
    extern __shared__ float sm[];
    float* Hb = sm;                  // h activations, transposed [HID][AP]
    float* Tb = sm + HID * AP;       // temps / state^T
    float* Wt = sm + 2 * HID * AP;   // weight chunk double buffer (2 x WBUF)

    const int tid = threadIdx.x;
    const int tm  = tid & 7;
    const int tn  = tid >> 3;        // 0..63, n base = tn*4
    const int wtb = tn * 4 * WCH;    // thread's W row-base offset inside a chunk
    const int xk  = (tn >> 1) & 7;   // XOR key: rows tn*4+j all have (n>>3)&7 == (tn>>1)&7
    const int m0  = blockIdx.x * MT;

    // ---- load state^T into Tb; zero rows 137..159 for the padded K=160 GEMM0 ----
    for (int idx = tid; idx < MT * SDIM; idx += NTHREADS) {
        int m = idx / SDIM;
        int k = idx - m * SDIM;
        Tb[k * AP + m] = state[(size_t)(m0 + m) * SDIM + k];
    }
    for (int idx = tid; idx < MT * 23; idx += NTHREADS) {
        int k = SDIM + (idx >> 6);
        int m = idx & 63;
        Tb[k * AP + m] = 0.f;
    }

    ull acc[4][4];

    // ---- GEMM0: Hb = relu(x @ W0^T + b0eff), K padded to 160 (W0 pitch 139) ----
    ZACC(acc);
    for (int c = 0; c < 5; c++) {
        __syncthreads();             // prior mm readers of Wt (and state writers at c=0) done
        int k0 = c * KC;
        for (int idx = tid; idx < HID * KC; idx += NTHREADS) {
            int r  = idx >> 5;
            int cc = idx & 31;
            int col = k0 + cc;
            Wt[wgrp(r, cc >> 2) + (cc & 3)] = (col < SDIM) ? W0[r * (SDIM + 2) + col] : 0.f;
        }
        __syncthreads();
        mm_chunk(Tb + c * KC * AP + tm * 4, Wt + wtb, xk, acc);
    }
#pragma unroll
    for (int j = 0; j < 4; j++) {
        int n = tn * 4 + j;
        float bb = g_b0eff[n];
        float2 p0 = unpk(acc[0][j]), p1 = unpk(acc[1][j]);
        float2 p2 = unpk(acc[2][j]), p3 = unpk(acc[3][j]);
        float4 v0 = make_float4(fmaxf(p0.x + bb, 0.f), fmaxf(p0.y + bb, 0.f),
                                fmaxf(p1.x + bb, 0.f), fmaxf(p1.y + bb, 0.f));
        float4 v1 = make_float4(fmaxf(p2.x + bb, 0.f), fmaxf(p2.y + bb, 0.f),
                                fmaxf(p3.x + bb, 0.f), fmaxf(p3.y + bb, 0.f));
        *(float4*)(Hb + n * AP + tm * 4)      = v0;
        *(float4*)(Hb + n * AP + 32 + tm * 4) = v1;
    }

    // ---- 4 residual blocks ----
    for (int blk = 0; blk < NBLK; blk++) {
        const float* W1 = blkW1 + blk * HID * HID;
        const float* W2 = blkW2 + blk * HID * HID;
        const float* b1 = blkb1 + blk * HID;
        const float* b2 = blkb2 + blk * HID;

        // Tb = tanh(Hb @ W1^T + b1)
        ZACC(acc);
        gemm_chunks(W1, HID / 4, HID, HID / KC, Hb, Wt, tid, tm, wtb, xk, acc);
#pragma unroll
        for (int j = 0; j < 4; j++) {
            int n = tn * 4 + j;
            float bb = b1[n];
            float2 p0 = unpk(acc[0][j]), p1 = unpk(acc[1][j]);
            float2 p2 = unpk(acc[2][j]), p3 = unpk(acc[3][j]);
            float4 v0 = make_float4(tanhf(p0.x + bb), tanhf(p0.y + bb),
                                    tanhf(p1.x + bb), tanhf(p1.y + bb));
            float4 v1 = make_float4(tanhf(p2.x + bb), tanhf(p2.y + bb),
                                    tanhf(p3.x + bb), tanhf(p3.y + bb));
            *(float4*)(Tb + n * AP + tm * 4)      = v0;
            *(float4*)(Tb + n * AP + 32 + tm * 4) = v1;
        }

        // Hb = tanh(Hb + Tb @ W2^T + b2)
        ZACC(acc);
        gemm_chunks(W2, HID / 4, HID, HID / KC, Tb, Wt, tid, tm, wtb, xk, acc);
#pragma unroll
        for (int j = 0; j < 4; j++) {
            int n = tn * 4 + j;
            float bb = b2[n];
            float2 p0 = unpk(acc[0][j]), p1 = unpk(acc[1][j]);
            float2 p2 = unpk(acc[2][j]), p3 = unpk(acc[3][j]);
            float4 o0 = *(const float4*)(Hb + n * AP + tm * 4);
            float4 o1 = *(const float4*)(Hb + n * AP + 32 + tm * 4);
            float4 v0 = make_float4(tanhf(o0.x + p0.x + bb), tanhf(o0.y + p0.y + bb),
                                    tanhf(o0.z + p1.x + bb), tanhf(o0.w + p1.y + bb));
            float4 v1 = make_float4(tanhf(o1.x + p2.x + bb), tanhf(o1.y + p2.y + bb),
                                    tanhf(o1.z + p3.x + bb), tanhf(o1.w + p3.y + bb));
            *(float4*)(Hb + n * AP + tm * 4)      = v0;
            *(float4*)(Hb + n * AP + 32 + tm * 4) = v1;
        }
    }

    // ---- reload state^T into Tb (rows 0..136) for the delta path ----
    for (int idx = tid; idx < MT * SDIM; idx += NTHREADS) {
        int m = idx / SDIM;
        int k = idx - m * SDIM;
        Tb[k * AP + m] = state[(size_t)(m0 + m) * SDIM + k];
    }

    // ---- core = Hb @ Wout^T + bout (rows >= 137 zero-filled) ----
    ZACC(acc);
    gemm_chunks(Wout, HID / 4, SDIM, HID / KC, Hb, Wt, tid, tm, wtb, xk, acc);

    // park core(+bout) in Hb (activations are dead) to free registers
#pragma unroll
    for (int j = 0; j < 4; j++) {
        int n = tn * 4 + j;
        float bo = (n < SDIM) ? bout[n] : 0.f;
        float2 p0 = unpk(acc[0][j]), p1 = unpk(acc[1][j]);
        float2 p2 = unpk(acc[2][j]), p3 = unpk(acc[3][j]);
        float4 v0 = make_float4(p0.x + bo, p0.y + bo, p1.x + bo, p1.y + bo);
        float4 v1 = make_float4(p2.x + bo, p2.y + bo, p3.x + bo, p3.y + bo);
        *(float4*)(Hb + n * AP + tm * 4)      = v0;
        *(float4*)(Hb + n * AP + 32 + tm * 4) = v1;
    }

    // ---- delta_h GEMM: acc = state[:, :128] @ M_ta^T (n >= 128 rows zero) ----
    ZACC(acc);
    gemm_chunks(g_Mta, AHD / 4, AHD, AHD / KC, Tb, Wt, tid, tm, wtb, xk, acc);

    // ---- combine + stage + store ----
    float* stage = Wt;               // 64 x 140 floats fits in 2*WBUF
#pragma unroll
    for (int j = 0; j < 4; j++) {
        int n = tn * 4 + j;
        if (n >= SDIM) continue;
        float2 q0 = unpk(acc[0][j]), q1 = unpk(acc[1][j]);
        float2 q2 = unpk(acc[2][j]), q3 = unpk(acc[3][j]);
        float dv[8] = { q0.x, q0.y, q1.x, q1.y, q2.x, q2.y, q3.x, q3.y };
#pragma unroll
        for (int mi = 0; mi < 8; mi++) {
            int m = (mi < 4) ? (tm * 4 + mi) : (32 + tm * 4 + (mi - 4));
            float core = Hb[n * AP + m];
            float val;
            if (n < AHD) {
                val = core + STRENGTH * (dv[mi] + g_cta[n] - Tb[n * AP + m]);
            } else if (n < SDIM - 1) {
                int jj = n - AHD;
                float d = g_clm[jj];
#pragma unroll
                for (int k = 0; k < ZED; k++)
                    d += g_Mlm[jj * ZED + k] * Tb[(AHD + k) * AP + m];
                val = core + STRENGTH * (d - Tb[n * AP + m]);
            } else {
                val = core;
            }
            stage[m * 140 + n] = val;
        }
    }
    __syncthreads();
    for (int idx = tid; idx < MT * SDIM; idx += NTHREADS) {
        int m = idx / SDIM;
        int c = idx - m * SDIM;
        out[(size_t)(m0 + m) * SDIM + c] = stage[m * 140 + c];
    }
}

// ---------------- launch ----------------
extern "C" void kernel_launch(void* const* d_in, const int* in_sizes, int n_in,
                              void* d_out, int out_size)
{
    const float* t        = (const float*)d_in[0];
    const float* state    = (const float*)d_in[1];
    const float* W0       = (const float*)d_in[2];
    const float* b0       = (const float*)d_in[3];
    const float* blkW1    = (const float*)d_in[4];
    const float* blkb1    = (const float*)d_in[5];
    const float* blkW2    = (const float*)d_in[6];
    const float* blkb2    = (const float*)d_in[7];
    const float* Wout     = (const float*)d_in[8];
    const float* bout     = (const float*)d_in[9];
    const float* lm_in_w  = (const float*)d_in[10];
    const float* lm_in_b  = (const float*)d_in[11];
    const float* lm_out_w = (const float*)d_in[12];
    const float* lm_out_b = (const float*)d_in[13];
    const float* ta_in_w  = (const float*)d_in[14];
    const float* ta_in_b  = (const float*)d_in[15];
    const float* ta_out_w = (const float*)d_in[16];
    const float* ta_out_b = (const float*)d_in[17];
    float* out = (float*)d_out;

    cudaFuncSetAttribute(fused_odefunc_kernel,
                         cudaFuncAttributeMaxDynamicSharedMemorySize, SMEM_BYTES);

    precompute_kernel<<<AHD + 2, 128>>>(t, W0, b0,
                                        lm_in_w, lm_in_b, lm_out_w, lm_out_b,
                                        ta_in_w, ta_in_b, ta_out_w, ta_out_b);

    fused_odefunc_kernel<<<B_TOTAL / MT, NTHREADS, SMEM_BYTES>>>(
        state, W0, blkW1, blkb1, blkW2, blkb2, Wout, bout, out);
}